// round 1
// baseline (speedup 1.0000x reference)
#include <cuda_runtime.h>
#include <math.h>

#define BS 64
#define NUM_CAMS 6
#define NJ 20
#define NPIX 4096          // 64*64
#define NMAPS (BS*NUM_CAMS*NJ)   // 7680

// Output layout (tuple order, flattened):
//   kp_3d : (BS, NJ, 3)            -> 3840
//   res   : (BS, NJ)               -> 1280
//   kpc   : (BS, NUM_CAMS, NJ, 3)  -> 23040
//   kph   : (BS, NUM_CAMS, NJ, 3)  -> 23040
#define OFF_KP3D 0
#define OFF_RES  (BS*NJ*3)                     // 3840
#define OFF_KPC  (OFF_RES + BS*NJ)             // 5120
#define OFF_KPH  (OFF_KPC + BS*NUM_CAMS*NJ*3)  // 28160

// ---------------------------------------------------------------------------
// Kernel 1: per-(cam-batch, joint) soft-argmax over 64x64 heatmap.
// One block (256 threads) per map; 16 values per thread, single HBM pass.
// ---------------------------------------------------------------------------
__global__ __launch_bounds__(256)
void softargmax_kernel(const float* __restrict__ hm, float* __restrict__ out)
{
    const int map = blockIdx.x;                 // 0..7679
    const float* p = hm + (size_t)map * NPIX;
    const int t = threadIdx.x;

    float vals[16];
    float lmax = -1e30f;
#pragma unroll
    for (int i = 0; i < 4; i++) {
        float4 v = reinterpret_cast<const float4*>(p)[i * 256 + t];
        vals[i*4+0] = v.x * 100.0f;
        vals[i*4+1] = v.y * 100.0f;
        vals[i*4+2] = v.z * 100.0f;
        vals[i*4+3] = v.w * 100.0f;
        lmax = fmaxf(lmax, fmaxf(fmaxf(vals[i*4+0], vals[i*4+1]),
                                 fmaxf(vals[i*4+2], vals[i*4+3])));
    }

    __shared__ float smax[8];
    __shared__ float sacc[3][8];

    const int wid  = t >> 5;
    const int lane = t & 31;

    // block max
#pragma unroll
    for (int o = 16; o > 0; o >>= 1)
        lmax = fmaxf(lmax, __shfl_xor_sync(0xffffffffu, lmax, o));
    if (lane == 0) smax[wid] = lmax;
    __syncthreads();
    float m;
    {
        float v0 = smax[0];
#pragma unroll
        for (int w = 1; w < 8; w++) v0 = fmaxf(v0, smax[w]);
        m = v0;
    }

    // exp + weighted sums. expf(x) == 0 exactly for x < ~-104, so skipping
    // those terms matches the reference bit-for-bit (mod summation order).
    float s = 0.f, sx = 0.f, sy = 0.f;
#pragma unroll
    for (int i = 0; i < 4; i++) {
#pragma unroll
        for (int u = 0; u < 4; u++) {
            float d = vals[i*4+u] - m;
            // warp-uniform skip: most warps have no surviving lane
            if (__ballot_sync(0xffffffffu, d > -104.0f)) {
                if (d > -104.0f) {
                    float e = expf(d);
                    int idx = i * 1024 + t * 4 + u;   // linear pixel index
                    s  += e;
                    sx += e * (float)(idx & 63);      // column (x)
                    sy += e * (float)(idx >> 6);      // row (y)
                }
            }
        }
    }

#pragma unroll
    for (int o = 16; o > 0; o >>= 1) {
        s  += __shfl_xor_sync(0xffffffffu, s,  o);
        sx += __shfl_xor_sync(0xffffffffu, sx, o);
        sy += __shfl_xor_sync(0xffffffffu, sy, o);
    }
    if (lane == 0) { sacc[0][wid] = s; sacc[1][wid] = sx; sacc[2][wid] = sy; }
    __syncthreads();

    if (t == 0) {
        float S = 0.f, X = 0.f, Y = 0.f;
#pragma unroll
        for (int w = 0; w < 8; w++) { S += sacc[0][w]; X += sacc[1][w]; Y += sacc[2][w]; }
        float recS = 1.0f / S;        // == max(softmax) (peak term is exp(0)=1)
        float x = X * recS;
        float y = Y * recS;
        float* kph = out + OFF_KPH + map * 3;
        float* kpc = out + OFF_KPC + map * 3;
        kph[0] = x;        kph[1] = y;        kph[2] = recS;
        kpc[0] = x * 4.0f; kpc[1] = y * 4.0f; kpc[2] = recS;   // 256/64 = 4
    }
}

// ---------------------------------------------------------------------------
// Kernel 2: per-(batch, joint) DLT triangulation via smallest eigenvector of
// AtA (4x4 symmetric, fp64 cyclic Jacobi, fully unrolled -> registers).
// ---------------------------------------------------------------------------
template<int P, int Q>
__device__ __forceinline__ void jrot(double M[4][4], double V[4][4])
{
    double apq = M[P][Q];
    if (apq != 0.0) {
        double app = M[P][P], aqq = M[Q][Q];
        double tau = (aqq - app) / (2.0 * apq);
        double t = ((tau >= 0.0) ? 1.0 : -1.0) / (fabs(tau) + sqrt(1.0 + tau * tau));
        double c = 1.0 / sqrt(1.0 + t * t);
        double s = t * c;

        M[P][P] = app - t * apq;
        M[Q][Q] = aqq + t * apq;
        M[P][Q] = 0.0; M[Q][P] = 0.0;
#pragma unroll
        for (int r = 0; r < 4; r++) {
            if (r != P && r != Q) {
                double arp = M[r][P], arq = M[r][Q];
                double np = c * arp - s * arq;
                double nq = s * arp + c * arq;
                M[r][P] = np; M[P][r] = np;
                M[r][Q] = nq; M[Q][r] = nq;
            }
        }
#pragma unroll
        for (int r = 0; r < 4; r++) {
            double vp = V[r][P], vq = V[r][Q];
            V[r][P] = c * vp - s * vq;
            V[r][Q] = s * vp + c * vq;
        }
    }
}

__global__ __launch_bounds__(64)
void triangulate_kernel(const float* __restrict__ proj,
                        const float* __restrict__ confid,
                        float* __restrict__ out)
{
    const int tidx = blockIdx.x * blockDim.x + threadIdx.x;
    if (tidx >= BS * NJ) return;
    const int b = tidx / NJ;
    const int j = tidx % NJ;

    // normalized per-camera confidences
    float cf[NUM_CAMS];
    float csum = 0.f;
#pragma unroll
    for (int c = 0; c < NUM_CAMS; c++) {
        cf[c] = confid[(b * NUM_CAMS + c) * NJ + j];
        csum += cf[c];
    }
#pragma unroll
    for (int c = 0; c < NUM_CAMS; c++) cf[c] = cf[c] / csum + 1e-5f;

    // Build A (12x4) in fp32 exactly like the reference
    const float* kpc = out + OFF_KPC;
    float Af[12][4];
#pragma unroll
    for (int c = 0; c < NUM_CAMS; c++) {
        const float* Pc = proj + (b * NUM_CAMS + c) * 12;
        const float px = kpc[((b * NUM_CAMS + c) * NJ + j) * 3 + 0];
        const float py = kpc[((b * NUM_CAMS + c) * NJ + j) * 3 + 1];
#pragma unroll
        for (int k = 0; k < 4; k++) {
            float r2 = Pc[8 + k];
            Af[c*2+0][k] = (r2 * px - Pc[0 + k]) * cf[c];
            Af[c*2+1][k] = (r2 * py - Pc[4 + k]) * cf[c];
        }
    }

    // M = A^T A in fp64
    double M[4][4], V[4][4];
#pragma unroll
    for (int k = 0; k < 4; k++)
#pragma unroll
        for (int l = 0; l < 4; l++) { M[k][l] = 0.0; V[k][l] = (k == l) ? 1.0 : 0.0; }
#pragma unroll
    for (int n = 0; n < 12; n++) {
#pragma unroll
        for (int k = 0; k < 4; k++) {
            double ak = (double)Af[n][k];
#pragma unroll
            for (int l = k; l < 4; l++)
                M[k][l] += ak * (double)Af[n][l];
        }
    }
#pragma unroll
    for (int k = 0; k < 4; k++)
#pragma unroll
        for (int l = 0; l < k; l++) M[k][l] = M[l][k];

    // 6 cyclic Jacobi sweeps (4x4 converges cubically; 6 is overkill-safe)
#pragma unroll
    for (int sweep = 0; sweep < 6; sweep++) {
        jrot<0,1>(M, V); jrot<0,2>(M, V); jrot<0,3>(M, V);
        jrot<1,2>(M, V); jrot<1,3>(M, V); jrot<2,3>(M, V);
    }

    // smallest eigenvalue -> smallest right singular vector of A
    int mi = 0; double dm = M[0][0];
    if (M[1][1] < dm) { dm = M[1][1]; mi = 1; }
    if (M[2][2] < dm) { dm = M[2][2]; mi = 2; }
    if (M[3][3] < dm) { dm = M[3][3]; mi = 3; }

    double v[4];
#pragma unroll
    for (int r = 0; r < 4; r++)
        v[r] = (mi == 0) ? V[r][0] : (mi == 1) ? V[r][1] : (mi == 2) ? V[r][2] : V[r][3];

    // kp_3d = homo[:3]/homo[3]; homo = -v, sign cancels
    double inv = 1.0 / v[3];
    float* kp3 = out + OFF_KP3D + tidx * 3;
    kp3[0] = (float)(v[0] * inv);
    kp3[1] = (float)(v[1] * inv);
    kp3[2] = (float)(v[2] * inv);

    // res = sum_n |A[n,:] . homo|  (abs -> sign-invariant)
    double acc = 0.0;
#pragma unroll
    for (int n = 0; n < 12; n++) {
        double dsum = (double)Af[n][0] * v[0] + (double)Af[n][1] * v[1]
                    + (double)Af[n][2] * v[2] + (double)Af[n][3] * v[3];
        acc += fabs(dsum);
    }
    out[OFF_RES + tidx] = (float)acc;
}

// ---------------------------------------------------------------------------
extern "C" void kernel_launch(void* const* d_in, const int* in_sizes, int n_in,
                              void* d_out, int out_size)
{
    const float* heatmap = (const float*)d_in[0];  // (384, 20, 64, 64)
    const float* proj    = (const float*)d_in[1];  // (64, 6, 3, 4)
    const float* confid  = (const float*)d_in[2];  // (384, 20)
    float* out = (float*)d_out;                    // 51200 floats

    softargmax_kernel<<<NMAPS, 256>>>(heatmap, out);
    triangulate_kernel<<<(BS * NJ + 63) / 64, 64>>>(proj, confid, out);
}

// round 2
// speedup vs baseline: 3.0114x; 3.0114x over previous
#include <cuda_runtime.h>
#include <math.h>

#define BS 64
#define NUM_CAMS 6
#define NJ 20
#define NPIX 4096          // 64*64
#define NMAPS (BS*NUM_CAMS*NJ)   // 7680

// Output layout (tuple order, flattened):
//   kp_3d : (BS, NJ, 3)            -> 3840
//   res   : (BS, NJ)               -> 1280
//   kpc   : (BS, NUM_CAMS, NJ, 3)  -> 23040
//   kph   : (BS, NUM_CAMS, NJ, 3)  -> 23040
#define OFF_KP3D 0
#define OFF_RES  (BS*NJ*3)                     // 3840
#define OFF_KPC  (OFF_RES + BS*NJ)             // 5120
#define OFF_KPH  (OFF_KPC + BS*NUM_CAMS*NJ*3)  // 28160

// ---------------------------------------------------------------------------
// Kernel 1: per-(cam-batch, joint) soft-argmax over 64x64 heatmap.
// One block (256 threads) per map; 16 values per thread, single HBM pass.
// ---------------------------------------------------------------------------
__global__ __launch_bounds__(256)
void softargmax_kernel(const float* __restrict__ hm, float* __restrict__ out)
{
    const int map = blockIdx.x;                 // 0..7679
    const float* p = hm + (size_t)map * NPIX;
    const int t = threadIdx.x;

    float vals[16];
    float lmax = -1e30f;
#pragma unroll
    for (int i = 0; i < 4; i++) {
        float4 v = reinterpret_cast<const float4*>(p)[i * 256 + t];
        vals[i*4+0] = v.x * 100.0f;
        vals[i*4+1] = v.y * 100.0f;
        vals[i*4+2] = v.z * 100.0f;
        vals[i*4+3] = v.w * 100.0f;
        lmax = fmaxf(lmax, fmaxf(fmaxf(vals[i*4+0], vals[i*4+1]),
                                 fmaxf(vals[i*4+2], vals[i*4+3])));
    }

    __shared__ float smax[8];
    __shared__ float sacc[3][8];

    const int wid  = t >> 5;
    const int lane = t & 31;

    // block max
#pragma unroll
    for (int o = 16; o > 0; o >>= 1)
        lmax = fmaxf(lmax, __shfl_xor_sync(0xffffffffu, lmax, o));
    if (lane == 0) smax[wid] = lmax;
    __syncthreads();
    float m;
    {
        float v0 = smax[0];
#pragma unroll
        for (int w = 1; w < 8; w++) v0 = fmaxf(v0, smax[w]);
        m = v0;
    }

    // exp + weighted sums. expf(x) == 0 exactly for x < ~-104, so skipping
    // those terms matches the reference bit-for-bit (mod summation order).
    float s = 0.f, sx = 0.f, sy = 0.f;
#pragma unroll
    for (int i = 0; i < 4; i++) {
#pragma unroll
        for (int u = 0; u < 4; u++) {
            float d = vals[i*4+u] - m;
            // warp-uniform skip: most warps have no surviving lane
            if (__ballot_sync(0xffffffffu, d > -104.0f)) {
                if (d > -104.0f) {
                    float e = expf(d);
                    int idx = i * 1024 + t * 4 + u;   // linear pixel index
                    s  += e;
                    sx += e * (float)(idx & 63);      // column (x)
                    sy += e * (float)(idx >> 6);      // row (y)
                }
            }
        }
    }

#pragma unroll
    for (int o = 16; o > 0; o >>= 1) {
        s  += __shfl_xor_sync(0xffffffffu, s,  o);
        sx += __shfl_xor_sync(0xffffffffu, sx, o);
        sy += __shfl_xor_sync(0xffffffffu, sy, o);
    }
    if (lane == 0) { sacc[0][wid] = s; sacc[1][wid] = sx; sacc[2][wid] = sy; }
    __syncthreads();

    if (t == 0) {
        float S = 0.f, X = 0.f, Y = 0.f;
#pragma unroll
        for (int w = 0; w < 8; w++) { S += sacc[0][w]; X += sacc[1][w]; Y += sacc[2][w]; }
        float recS = 1.0f / S;        // == max(softmax) (peak term is exp(0)=1)
        float x = X * recS;
        float y = Y * recS;
        float* kph = out + OFF_KPH + map * 3;
        float* kpc = out + OFF_KPC + map * 3;
        kph[0] = x;        kph[1] = y;        kph[2] = recS;
        kpc[0] = x * 4.0f; kpc[1] = y * 4.0f; kpc[2] = recS;   // 256/64 = 4
    }
}

// ---------------------------------------------------------------------------
// Kernel 2: per-(batch, joint) DLT triangulation.
//   Stage A: fp32 cyclic Jacobi on AtA (fast, FMA pipe) -> eigen estimate
//   Stage B: fp64 inverse iteration x2 (unpivoted LU of PSD AtA, reciprocal
//            pivots cached) -> fp64-accurate smallest eigenvector
// ---------------------------------------------------------------------------
template<int P, int Q>
__device__ __forceinline__ void jrotf(float M[4][4], float V[4][4])
{
    float apq = M[P][Q];
    if (apq != 0.0f) {
        float app = M[P][P], aqq = M[Q][Q];
        float tau = (aqq - app) / (2.0f * apq);
        float tt  = ((tau >= 0.0f) ? 1.0f : -1.0f) /
                    (fabsf(tau) + sqrtf(1.0f + tau * tau));
        float c = rsqrtf(1.0f + tt * tt);
        float s = tt * c;

        M[P][P] = app - tt * apq;
        M[Q][Q] = aqq + tt * apq;
        M[P][Q] = 0.0f; M[Q][P] = 0.0f;
#pragma unroll
        for (int r = 0; r < 4; r++) {
            if (r != P && r != Q) {
                float arp = M[r][P], arq = M[r][Q];
                float np = c * arp - s * arq;
                float nq = s * arp + c * arq;
                M[r][P] = np; M[P][r] = np;
                M[r][Q] = nq; M[Q][r] = nq;
            }
        }
#pragma unroll
        for (int r = 0; r < 4; r++) {
            float vp = V[r][P], vq = V[r][Q];
            V[r][P] = c * vp - s * vq;
            V[r][Q] = s * vp + c * vq;
        }
    }
}

__global__ __launch_bounds__(32)
void triangulate_kernel(const float* __restrict__ proj,
                        const float* __restrict__ confid,
                        float* __restrict__ out)
{
    const int tidx = blockIdx.x * blockDim.x + threadIdx.x;
    if (tidx >= BS * NJ) return;
    const int b = tidx / NJ;
    const int j = tidx % NJ;

    // normalized per-camera confidences
    float cf[NUM_CAMS];
    float csum = 0.f;
#pragma unroll
    for (int c = 0; c < NUM_CAMS; c++) {
        cf[c] = confid[(b * NUM_CAMS + c) * NJ + j];
        csum += cf[c];
    }
#pragma unroll
    for (int c = 0; c < NUM_CAMS; c++) cf[c] = cf[c] / csum + 1e-5f;

    // Build A (12x4) in fp32 exactly like the reference
    const float* kpc = out + OFF_KPC;
    float Af[12][4];
#pragma unroll
    for (int c = 0; c < NUM_CAMS; c++) {
        const float* Pc = proj + (b * NUM_CAMS + c) * 12;
        const float px = kpc[((b * NUM_CAMS + c) * NJ + j) * 3 + 0];
        const float py = kpc[((b * NUM_CAMS + c) * NJ + j) * 3 + 1];
#pragma unroll
        for (int k = 0; k < 4; k++) {
            float r2 = Pc[8 + k];
            Af[c*2+0][k] = (r2 * px - Pc[0 + k]) * cf[c];
            Af[c*2+1][k] = (r2 * py - Pc[4 + k]) * cf[c];
        }
    }

    // ---------------- Stage A: fp32 Jacobi on M32 = AtA -------------------
    float M32[4][4], V32[4][4];
#pragma unroll
    for (int k = 0; k < 4; k++)
#pragma unroll
        for (int l = 0; l < 4; l++) { M32[k][l] = 0.0f; V32[k][l] = (k == l) ? 1.0f : 0.0f; }
#pragma unroll
    for (int n = 0; n < 12; n++) {
#pragma unroll
        for (int k = 0; k < 4; k++) {
            float ak = Af[n][k];
#pragma unroll
            for (int l = k; l < 4; l++)
                M32[k][l] = fmaf(ak, Af[n][l], M32[k][l]);
        }
    }
#pragma unroll
    for (int k = 0; k < 4; k++)
#pragma unroll
        for (int l = 0; l < k; l++) M32[k][l] = M32[l][k];

#pragma unroll
    for (int sweep = 0; sweep < 5; sweep++) {
        jrotf<0,1>(M32, V32); jrotf<0,2>(M32, V32); jrotf<0,3>(M32, V32);
        jrotf<1,2>(M32, V32); jrotf<1,3>(M32, V32); jrotf<2,3>(M32, V32);
    }

    int mi = 0; float dmf = M32[0][0];
    if (M32[1][1] < dmf) { dmf = M32[1][1]; mi = 1; }
    if (M32[2][2] < dmf) { dmf = M32[2][2]; mi = 2; }
    if (M32[3][3] < dmf) { dmf = M32[3][3]; mi = 3; }

    // starting vector for inverse iteration (fp32 estimate, promoted)
    double x[4];
#pragma unroll
    for (int r = 0; r < 4; r++) {
        float vr = (mi == 0) ? V32[r][0] : (mi == 1) ? V32[r][1]
                 : (mi == 2) ? V32[r][2] : V32[r][3];
        x[r] = (double)vr;
    }

    // ---------------- Stage B: fp64 M, LU (no pivot, PSD), 2 solves -------
    double M[4][4];
#pragma unroll
    for (int k = 0; k < 4; k++)
#pragma unroll
        for (int l = 0; l < 4; l++) M[k][l] = 0.0;
#pragma unroll
    for (int n = 0; n < 12; n++) {
#pragma unroll
        for (int k = 0; k < 4; k++) {
            double ak = (double)Af[n][k];
#pragma unroll
            for (int l = k; l < 4; l++)
                M[k][l] = fma(ak, (double)Af[n][l], M[k][l]);
        }
    }
#pragma unroll
    for (int k = 0; k < 4; k++)
#pragma unroll
        for (int l = 0; l < k; l++) M[k][l] = M[l][k];

    // in-place LU: L strictly below diag (unit), U on/above. rcp of pivots cached.
    double rcp[4];
#pragma unroll
    for (int k = 0; k < 4; k++) {
        rcp[k] = 1.0 / M[k][k];
#pragma unroll
        for (int i = k + 1; i < 4; i++) {
            double l = M[i][k] * rcp[k];
            M[i][k] = l;
#pragma unroll
            for (int jj = k + 1; jj < 4; jj++)
                M[i][jj] = fma(-l, M[k][jj], M[i][jj]);
        }
    }

    // two inverse-iteration steps: x <- U^-1 L^-1 x  (growth bounded, no
    // intermediate normalization needed in fp64)
#pragma unroll
    for (int it = 0; it < 2; it++) {
        // forward: L y = x (unit diag)
        double y0 = x[0];
        double y1 = fma(-M[1][0], y0, x[1]);
        double y2 = fma(-M[2][1], y1, fma(-M[2][0], y0, x[2]));
        double y3 = fma(-M[3][2], y2, fma(-M[3][1], y1, fma(-M[3][0], y0, x[3])));
        // backward: U x = y
        double x3 = y3 * rcp[3];
        double x2 = fma(-M[2][3], x3, y2) * rcp[2];
        double x1 = fma(-M[1][3], x3, fma(-M[1][2], x2, y1)) * rcp[1];
        double x0 = fma(-M[0][3], x3, fma(-M[0][2], x2, fma(-M[0][1], x1, y0))) * rcp[0];
        x[0] = x0; x[1] = x1; x[2] = x2; x[3] = x3;
    }

    // unit 2-norm (res_triang is scale-dependent; reference uses unit vh row)
    double nrm2 = fma(x[0], x[0], fma(x[1], x[1], fma(x[2], x[2], x[3] * x[3])));
    double inrm = 1.0 / sqrt(nrm2);
    double v[4] = { x[0] * inrm, x[1] * inrm, x[2] * inrm, x[3] * inrm };

    // kp_3d = homo[:3]/homo[3]; homo = -v, sign cancels
    double inv = 1.0 / v[3];
    float* kp3 = out + OFF_KP3D + tidx * 3;
    kp3[0] = (float)(v[0] * inv);
    kp3[1] = (float)(v[1] * inv);
    kp3[2] = (float)(v[2] * inv);

    // res = sum_n |A[n,:] . homo|  (abs -> sign-invariant)
    double acc = 0.0;
#pragma unroll
    for (int n = 0; n < 12; n++) {
        double dsum = fma((double)Af[n][0], v[0],
                      fma((double)Af[n][1], v[1],
                      fma((double)Af[n][2], v[2], (double)Af[n][3] * v[3])));
        acc += fabs(dsum);
    }
    out[OFF_RES + tidx] = (float)acc;
}

// ---------------------------------------------------------------------------
extern "C" void kernel_launch(void* const* d_in, const int* in_sizes, int n_in,
                              void* d_out, int out_size)
{
    const float* heatmap = (const float*)d_in[0];  // (384, 20, 64, 64)
    const float* proj    = (const float*)d_in[1];  // (64, 6, 3, 4)
    const float* confid  = (const float*)d_in[2];  // (384, 20)
    float* out = (float*)d_out;                    // 51200 floats

    softargmax_kernel<<<NMAPS, 256>>>(heatmap, out);
    triangulate_kernel<<<(BS * NJ + 31) / 32, 32>>>(proj, confid, out);
}